// round 1
// baseline (speedup 1.0000x reference)
#include <cuda_runtime.h>

#define BB   2
#define SS   2048
#define DD   1024
#define HH   16
#define KVHn 4
#define HD   64
#define WIN  64
#define MM   (BB*SS)   // 4096

// Scratch (allocation-free rule: __device__ globals)
__device__ float g_q[MM * HH * HD];     // [b*S+s][h*64+d] after RoPE
__device__ float g_k[MM * KVHn * HD];   // [b*S+s][kvh*64+d] after RoPE
__device__ float g_v[MM * KVHn * HD];
__device__ float g_att[MM * HH * HD];   // attention output before Wo

// ---------------------------------------------------------------------------
// Kernel 1: fused QKV projection + RoPE epilogue.
// C[4096,1536] = x[4096,1024] @ [wq | wk | wv], 64x64 block tile, BK=16,
// 256 threads, 4x4 micro-tile. Smem row stride 68 floats (272B, 16B-aligned,
// 68 % 32 == 4 -> conflict-free transposed STS of the A tile).
// ---------------------------------------------------------------------------
__global__ __launch_bounds__(256) void qkv_rope_kernel(
    const float* __restrict__ x,  const float* __restrict__ wq,
    const float* __restrict__ wk, const float* __restrict__ wv,
    const float* __restrict__ fc, const float* __restrict__ fs)
{
    __shared__ float As[16 * 68];
    __shared__ float Bs[16 * 68];
    const int tid = threadIdx.x;
    const int tx = tid & 15, ty = tid >> 4;
    const int m0 = blockIdx.y * 64;
    const int n0 = blockIdx.x * 64;

    // Whole 64-wide N tile lives in exactly one of wq/wk/wv (segment bounds
    // 1024 and 1280 are 64-aligned).
    const float* bsrc; int ldb, boff;
    if (n0 < 1024)      { bsrc = wq; ldb = 1024; boff = n0; }
    else if (n0 < 1280) { bsrc = wk; ldb = 256;  boff = n0 - 1024; }
    else                { bsrc = wv; ldb = 256;  boff = n0 - 1280; }

    const int ar = tid >> 2, ak = (tid & 3) * 4;   // A tile: 64 rows x 4 float4
    const int bk = tid >> 4, bn = (tid & 15) * 4;  // B tile: 16 rows x 16 float4

    float acc[4][4];
    #pragma unroll
    for (int i = 0; i < 4; i++)
        #pragma unroll
        for (int j = 0; j < 4; j++) acc[i][j] = 0.f;

    for (int k0 = 0; k0 < 1024; k0 += 16) {
        float4 av = *(const float4*)&x[(m0 + ar) * 1024 + k0 + ak];
        As[(ak + 0) * 68 + ar] = av.x;
        As[(ak + 1) * 68 + ar] = av.y;
        As[(ak + 2) * 68 + ar] = av.z;
        As[(ak + 3) * 68 + ar] = av.w;
        *(float4*)&Bs[bk * 68 + bn] =
            *(const float4*)&bsrc[(k0 + bk) * ldb + boff + bn];
        __syncthreads();
        #pragma unroll
        for (int kk = 0; kk < 16; ++kk) {
            float4 a = *(const float4*)&As[kk * 68 + ty * 4];
            float4 b = *(const float4*)&Bs[kk * 68 + tx * 4];
            float av4[4] = {a.x, a.y, a.z, a.w};
            float bv4[4] = {b.x, b.y, b.z, b.w};
            #pragma unroll
            for (int i = 0; i < 4; i++)
                #pragma unroll
                for (int j = 0; j < 4; j++)
                    acc[i][j] += av4[i] * bv4[j];
        }
        __syncthreads();
    }

    // Epilogue: RoPE on q/k column pairs (thread owns 4 consecutive cols,
    // 2 rope pairs), plain store for v.
    #pragma unroll
    for (int r = 0; r < 4; r++) {
        int row = m0 + ty * 4 + r;
        int s = row & (SS - 1);
        #pragma unroll
        for (int cp = 0; cp < 2; cp++) {
            float a  = acc[r][cp * 2];
            float b2 = acc[r][cp * 2 + 1];
            int n = n0 + tx * 4 + cp * 2;
            if (n < 1024) {
                int d = n & 63, j = d >> 1;
                float c = fc[s * 32 + j], sn = fs[s * 32 + j];
                g_q[row * 1024 + n]     = a * c  - b2 * sn;
                g_q[row * 1024 + n + 1] = a * sn + b2 * c;
            } else if (n < 1280) {
                int nn = n - 1024, d = nn & 63, j = d >> 1;
                float c = fc[s * 32 + j], sn = fs[s * 32 + j];
                g_k[row * 256 + nn]     = a * c  - b2 * sn;
                g_k[row * 256 + nn + 1] = a * sn + b2 * c;
            } else {
                int nn = n - 1280;
                g_v[row * 256 + nn]     = a;
                g_v[row * 256 + nn + 1] = b2;
            }
        }
    }
}

// ---------------------------------------------------------------------------
// Kernel 2: sliding-window attention.
// Block = (b, kvh, 16-query tile). K/V window (<=80 rows) in smem, shared by
// all 4 GQA rep-heads. 2 threads per (query, head): each owns half of HD.
// Online softmax; lane-pair shfl combines the two half-dot-products.
// ---------------------------------------------------------------------------
__global__ __launch_bounds__(128) void attn_kernel()
{
    __shared__ float Ks[80 * 68];
    __shared__ float Vs[80 * 68];
    const int b   = blockIdx.z;
    const int kvh = blockIdx.y;
    const int qbase  = blockIdx.x * 16;
    const int kstart = max(0, qbase - WIN);
    const int nrows  = qbase + 16 - kstart;    // <= 80
    const int tid = threadIdx.x;

    for (int i = tid; i < nrows * 16; i += 128) {
        int row = i >> 4, c = (i & 15) * 4;
        int gidx = ((b * SS + kstart + row) * KVHn + kvh) * 64 + c;
        *(float4*)&Ks[row * 68 + c] = *(const float4*)&g_k[gidx];
        *(float4*)&Vs[row * 68 + c] = *(const float4*)&g_v[gidx];
    }
    __syncthreads();

    const int half = tid & 1, pair = tid >> 1;
    const int rep = pair & 3, qi = pair >> 2;
    const int qg = qbase + qi;
    const int h  = kvh * 4 + rep;              // q-head h uses kv-head h/4
    // Pair-scoped shfl mask: the two half-threads of a (query,head) are
    // always converged; full-warp mask would be illegal (per-query loop trip
    // counts differ inside a warp).
    const unsigned pmask = 3u << ((tid & 31) & ~1);

    float qreg[32];
    const float* qp = &g_q[((b * SS + qg) * HH + h) * 64 + half * 32];
    #pragma unroll
    for (int d = 0; d < 32; d++) qreg[d] = qp[d];

    float accv[32];
    #pragma unroll
    for (int d = 0; d < 32; d++) accv[d] = 0.f;
    float m = -1e30f, l = 0.f;

    const int j0 = max(0, qg - WIN) - kstart;
    const int j1 = qg - kstart;
    for (int j = j0; j <= j1; ++j) {
        const float* kr = &Ks[j * 68 + half * 32];
        float partial = 0.f;
        #pragma unroll
        for (int d = 0; d < 32; d++) partial += qreg[d] * kr[d];
        float sc = (partial + __shfl_xor_sync(pmask, partial, 1)) * 0.125f;
        float mn  = fmaxf(m, sc);
        float esc = __expf(m - mn);
        float p   = __expf(sc - mn);
        l = l * esc + p;
        const float* vr = &Vs[j * 68 + half * 32];
        #pragma unroll
        for (int d = 0; d < 32; d++) accv[d] = accv[d] * esc + p * vr[d];
        m = mn;
    }
    float inv = 1.f / l;
    float* op = &g_att[(b * SS + qg) * 1024 + h * 64 + half * 32];
    #pragma unroll
    for (int d = 0; d < 32; d++) op[d] = accv[d] * inv;
}

// ---------------------------------------------------------------------------
// Kernel 3: output projection. out[4096,1024] = g_att @ wo. Same SGEMM.
// ---------------------------------------------------------------------------
__global__ __launch_bounds__(256) void oproj_kernel(
    const float* __restrict__ wo, float* __restrict__ out)
{
    __shared__ float As[16 * 68];
    __shared__ float Bs[16 * 68];
    const int tid = threadIdx.x;
    const int tx = tid & 15, ty = tid >> 4;
    const int m0 = blockIdx.y * 64;
    const int n0 = blockIdx.x * 64;

    const int ar = tid >> 2, ak = (tid & 3) * 4;
    const int bk = tid >> 4, bn = (tid & 15) * 4;

    float acc[4][4];
    #pragma unroll
    for (int i = 0; i < 4; i++)
        #pragma unroll
        for (int j = 0; j < 4; j++) acc[i][j] = 0.f;

    for (int k0 = 0; k0 < 1024; k0 += 16) {
        float4 av = *(const float4*)&g_att[(m0 + ar) * 1024 + k0 + ak];
        As[(ak + 0) * 68 + ar] = av.x;
        As[(ak + 1) * 68 + ar] = av.y;
        As[(ak + 2) * 68 + ar] = av.z;
        As[(ak + 3) * 68 + ar] = av.w;
        *(float4*)&Bs[bk * 68 + bn] =
            *(const float4*)&wo[(k0 + bk) * 1024 + n0 + bn];
        __syncthreads();
        #pragma unroll
        for (int kk = 0; kk < 16; ++kk) {
            float4 a = *(const float4*)&As[kk * 68 + ty * 4];
            float4 b = *(const float4*)&Bs[kk * 68 + tx * 4];
            float av4[4] = {a.x, a.y, a.z, a.w};
            float bv4[4] = {b.x, b.y, b.z, b.w};
            #pragma unroll
            for (int i = 0; i < 4; i++)
                #pragma unroll
                for (int j = 0; j < 4; j++)
                    acc[i][j] += av4[i] * bv4[j];
        }
        __syncthreads();
    }

    #pragma unroll
    for (int r = 0; r < 4; r++) {
        int row = m0 + ty * 4 + r;
        #pragma unroll
        for (int j = 0; j < 4; j++)
            out[row * 1024 + n0 + tx * 4 + j] = acc[r][j];
    }
}

// ---------------------------------------------------------------------------
extern "C" void kernel_launch(void* const* d_in, const int* in_sizes, int n_in,
                              void* d_out, int out_size)
{
    const float* x  = (const float*)d_in[0];
    const float* fc = (const float*)d_in[1];
    const float* fs = (const float*)d_in[2];
    const float* wq = (const float*)d_in[3];
    const float* wk = (const float*)d_in[4];
    const float* wv = (const float*)d_in[5];
    const float* wo = (const float*)d_in[6];
    float* out = (float*)d_out;

    qkv_rope_kernel<<<dim3(24, 64), 256>>>(x, wq, wk, wv, fc, fs);
    attn_kernel<<<dim3(SS / 16, KVHn, BB), 128>>>();
    oproj_kernel<<<dim3(16, 64), 256>>>(wo, out);
}